// round 12
// baseline (speedup 1.0000x reference)
#include <cuda_runtime.h>
#include <cuda_bf16.h>
#include <cstdint>

#define N_VOX   400000
#define MTILE   384
#define THREADS 768
#define NTILES  1042          // ceil(400000/384)
#define KK      27

// SMEM: [0) gamma 128B | [128) beta 128B | [256) flags 24*4B | [1024) W 27*4096B | [111616) A 384*128B
#define SM_G     0
#define SM_BETA  128
#define SM_FLAGS 256
#define SM_W     1024
#define SM_A     111616
#define SMEM_TOTAL (SM_A + MTILE * 128)   // 160768

__device__ float g_h[(size_t)N_VOX * 32];

static __device__ __forceinline__ uint32_t smem_u32(const void* p) {
    uint32_t a;
    asm("{ .reg .u64 t; cvta.to.shared.u64 t, %1; cvt.u32.u64 %0, t; }" : "=r"(a) : "l"(p));
    return a;
}
static __device__ __forceinline__ uint32_t pk2(float a, float b) {
    __nv_bfloat162 h = __floats2bfloat162_rn(a, b);
    return *reinterpret_cast<uint32_t*>(&h);
}
static __device__ __forceinline__ float bfh(float x) {
    return __bfloat162float(__float2bfloat16_rn(x));
}
static __device__ __forceinline__ void ldsm4(uint32_t* r, uint32_t addr) {
    asm volatile("ldmatrix.sync.aligned.m8n8.x4.shared.b16 {%0,%1,%2,%3}, [%4];"
                 : "=r"(r[0]), "=r"(r[1]), "=r"(r[2]), "=r"(r[3]) : "r"(addr));
}
static __device__ __forceinline__ void mma16816(float* d, const uint32_t* a,
                                                uint32_t b0, uint32_t b1) {
    asm volatile("mma.sync.aligned.m16n8k16.row.col.f32.bf16.bf16.f32 "
                 "{%0,%1,%2,%3},{%4,%5,%6,%7},{%8,%9},{%0,%1,%2,%3};"
                 : "+f"(d[0]), "+f"(d[1]), "+f"(d[2]), "+f"(d[3])
                 : "r"(a[0]), "r"(a[1]), "r"(a[2]), "r"(a[3]), "r"(b0), "r"(b1));
}
static __device__ __forceinline__ void bar_pair(int id) {
    asm volatile("bar.sync %0, %1;" :: "r"(id), "r"(64) : "memory");
}

template <bool FINAL>
__global__ void __launch_bounds__(THREADS, 1)
conv_hmma(const float* __restrict__ feats, const float* __restrict__ resid,
          const int* __restrict__ nbr, const float* __restrict__ Wg,
          const float* __restrict__ gamma, const float* __restrict__ beta,
          float* __restrict__ out)
{
    extern __shared__ char smem[];
    const uint32_t sb  = smem_u32(smem);
    const int tid  = threadIdx.x, wid = tid >> 5, lane = tid & 31;
    const int rw   = wid % 12;          // row-warp index (pair id)
    const int nh   = wid / 12;          // N-half: 0 -> cols 0-15, 1 -> cols 16-31
    const int pidx = lane + (nh << 5);  // 0..63 within pair
    const int row  = rw * 32 + (pidx >> 1);   // my pack/LN row within tile
    const int hh   = lane & 1;                // 64B half of the row I own

    if (tid < 32) {
        ((float*)(smem + SM_G))[tid]    = gamma[tid];
        ((float*)(smem + SM_BETA))[tid] = beta[tid];
    }

    // ---- W prep: [k][cin][cout] -> rows of cout: [Wh 64B | Wl 64B], chunk-swizzled ----
    {
        float* stage = (float*)(smem + SM_A);
        for (int k = 0; k < KK; k++) {
            stage[tid] = Wg[k * 1024 + tid];
            if (tid < 256) stage[768 + tid] = Wg[k * 1024 + 768 + tid];
            __syncthreads();
            if (tid < 256) {
                const int cout = tid & 31, g4 = tid >> 5;   // g4: group of 4 cins
                float w[4], wh[4];
                #pragma unroll
                for (int j = 0; j < 4; j++) {
                    w[j]  = stage[(g4 * 4 + j) * 32 + cout];
                    wh[j] = bfh(w[j]);
                }
                uint2 hi = make_uint2(pk2(w[0], w[1]), pk2(w[2], w[3]));
                uint2 lo = make_uint2(pk2(w[0]-wh[0], w[1]-wh[1]), pk2(w[2]-wh[2], w[3]-wh[3]));
                char* wk = smem + SM_W + k * 4096 + cout * 128;
                const int s = cout & 7, ch = g4 >> 1, half8 = (g4 & 1) * 8;
                *(uint2*)(wk + ((ch ^ s) << 4) + half8)       = hi;
                *(uint2*)(wk + (((4 + ch) ^ s) << 4) + half8) = lo;
            }
            __syncthreads();
        }
    }

    const uint32_t a_base = sb + SM_A;
    uint32_t* flags = (uint32_t*)(smem + SM_FLAGS);
    // LDSM lane constants
    const int b_nrow = nh * 16 + (lane & 7) + ((lane >> 4) << 3);
    const int b_chof = (lane >> 3) & 1;
    const int a_rofs = (lane & 7) + (lane & 8);
    const int a_chof = (lane >> 4);
    const int barid  = 1 + rw;

    for (int tile = blockIdx.x; tile < NTILES; tile += gridDim.x) {
        const int base = tile * MTILE;
        const int gidx = base + row;
        const bool inb = gidx < N_VOX;

        float acc[2][2][4];
        #pragma unroll
        for (int mi = 0; mi < 2; mi++)
            #pragma unroll
            for (int nb = 0; nb < 2; nb++)
                #pragma unroll
                for (int q = 0; q < 4; q++) acc[mi][nb][q] = 0.f;

        int i0 = inb ? nbr[gidx] : -1;
        int i1 = inb ? nbr[N_VOX + gidx] : -1;
        float4 f[4];
        {
            const float4* p = (const float4*)(feats + (size_t)(i0 >= 0 ? i0 : 0) * 32 + hh * 16);
            #pragma unroll
            for (int j = 0; j < 4; j++) f[j] = (i0 >= 0) ? p[j] : make_float4(0.f,0.f,0.f,0.f);
        }

        #pragma unroll 1
        for (int k = 0; k < KK; k++) {
            const int i2 = (k + 2 < KK && inb) ? nbr[(size_t)(k + 2) * N_VOX + gidx] : -1;
            const bool act = (i0 >= 0);

            bar_pair(barid);   // prior tap's LDSM / LN reads done before overwrite
            const uint32_t mask = __ballot_sync(0xffffffffu, act);
            if (mask) {        // my 16-row group is consumed -> store my half (zeros ok)
                uint32_t hi[8], lo[8];
                if (act) {
                    #pragma unroll
                    for (int j = 0; j < 4; j++) {
                        float4 q = f[j];
                        float hx = bfh(q.x), hy = bfh(q.y), hz = bfh(q.z), hw = bfh(q.w);
                        hi[2*j]   = pk2(q.x, q.y);       hi[2*j+1] = pk2(q.z, q.w);
                        lo[2*j]   = pk2(q.x-hx, q.y-hy); lo[2*j+1] = pk2(q.z-hz, q.w-hw);
                    }
                } else {
                    #pragma unroll
                    for (int j = 0; j < 8; j++) { hi[j] = 0u; lo[j] = 0u; }
                }
                char* arow = smem + SM_A + row * 128;
                const int s = row & 7;
                const int c0 = hh * 2;
                *(uint4*)(arow + (((c0    ) ^ s) << 4)) = make_uint4(hi[0], hi[1], hi[2], hi[3]);
                *(uint4*)(arow + (((c0 + 1) ^ s) << 4)) = make_uint4(hi[4], hi[5], hi[6], hi[7]);
                *(uint4*)(arow + (((4 + c0    ) ^ s) << 4)) = make_uint4(lo[0], lo[1], lo[2], lo[3]);
                *(uint4*)(arow + (((4 + c0 + 1) ^ s) << 4)) = make_uint4(lo[4], lo[5], lo[6], lo[7]);
            }
            if (lane == 0) flags[wid] = mask;

            // prefetch next tap's features (f consumed by pack above)
            {
                const bool an = (i1 >= 0);
                const float4* p = (const float4*)(feats + (size_t)(an ? i1 : 0) * 32 + hh * 16);
                #pragma unroll
                for (int j = 0; j < 4; j++) f[j] = an ? p[j] : make_float4(0.f,0.f,0.f,0.f);
            }

            bar_pair(barid);   // A tile + flags visible to both warps of the pair
            const uint32_t m0 = flags[rw], m1 = flags[rw + 12];
            if (m0 | m1) {
                uint32_t bh[2][4], bl[2][4];
                const uint32_t wbase = sb + SM_W + k * 4096;
                {
                    const int n0 = b_nrow, s = n0 & 7;
                    const uint32_t rb = wbase + n0 * 128;
                    #pragma unroll
                    for (int kb = 0; kb < 2; kb++) {
                        ldsm4(bh[kb], rb + (((2*kb + b_chof) ^ s) << 4));
                        ldsm4(bl[kb], rb + (((4 + 2*kb + b_chof) ^ s) << 4));
                    }
                }
                #pragma unroll
                for (int mi = 0; mi < 2; mi++) {
                    const uint32_t mm = mi ? m1 : m0;
                    if (mm) {
                        uint32_t ah[8], al[8];
                        const int arow = rw * 32 + mi * 16 + a_rofs;
                        const int s    = arow & 7;
                        const uint32_t ra = a_base + arow * 128;
                        #pragma unroll
                        for (int kb = 0; kb < 2; kb++) {
                            ldsm4(ah + kb*4, ra + (((2*kb + a_chof) ^ s) << 4));
                            ldsm4(al + kb*4, ra + (((4 + 2*kb + a_chof) ^ s) << 4));
                        }
                        #pragma unroll
                        for (int nb = 0; nb < 2; nb++) {
                            const int sel = nb * 2;
                            #pragma unroll
                            for (int kb = 0; kb < 2; kb++) {
                                mma16816(acc[mi][nb], ah + kb*4, bh[kb][sel], bh[kb][sel+1]);
                                mma16816(acc[mi][nb], al + kb*4, bh[kb][sel], bh[kb][sel+1]);
                                mma16816(acc[mi][nb], ah + kb*4, bl[kb][sel], bl[kb][sel+1]);
                            }
                        }
                    }
                }
            }
            i0 = i1; i1 = i2;
        }

        // ---- epilogue: acc frags -> fp32 rows in SMEM -> per-half-row LN ----
        bar_pair(barid);       // pair's last LDSM of A done before overwrite
        {
            const int r0 = rw * 32 + (lane >> 2);
            const int cb = (lane & 3) * 8;
            #pragma unroll
            for (int mi = 0; mi < 2; mi++) {
                const int rr = r0 + mi * 16;
                const int s  = rr & 7;                      // (rr+8)&7 == rr&7
                char* rp  = smem + SM_A + rr * 128;
                char* rp8 = smem + SM_A + (rr + 8) * 128;
                #pragma unroll
                for (int nb = 0; nb < 2; nb++) {
                    const int byte0 = nh * 64 + nb * 32 + cb;
                    const int ch = byte0 >> 4, off = byte0 & 15;
                    *(float2*)(rp  + ((ch ^ s) << 4) + off) = make_float2(acc[mi][nb][0], acc[mi][nb][1]);
                    *(float2*)(rp8 + ((ch ^ s) << 4) + off) = make_float2(acc[mi][nb][2], acc[mi][nb][3]);
                }
            }
        }
        bar_pair(barid);
        if (inb) {
            float v[16];
            const int s = row & 7;
            const char* rp = smem + SM_A + row * 128;
            #pragma unroll
            for (int j = 0; j < 4; j++) {
                const int c = hh * 4 + j;
                float4 t4 = *(const float4*)(rp + ((c ^ s) << 4));
                v[4*j] = t4.x; v[4*j+1] = t4.y; v[4*j+2] = t4.z; v[4*j+3] = t4.w;
            }
            float sum = 0.f;
            #pragma unroll
            for (int c = 0; c < 16; c++) sum += v[c];
            sum += __shfl_xor_sync(0xffffffffu, sum, 1);    // partner lane = other half of row
            const float mu = sum * (1.0f / 32.0f);
            float var = 0.f;
            #pragma unroll
            for (int c = 0; c < 16; c++) { float d = v[c] - mu; var += d * d; }
            var += __shfl_xor_sync(0xffffffffu, var, 1);
            const float rs = rsqrtf(var * (1.0f / 32.0f) + 1e-6f);
            const float* gs = (const float*)(smem + SM_G)    + hh * 16;
            const float* bs = (const float*)(smem + SM_BETA) + hh * 16;
            float4* op = (float4*)(out + (size_t)gidx * 32 + hh * 16);
            const float4* rpg = FINAL ? (const float4*)(resid + (size_t)gidx * 32 + hh * 16) : nullptr;
            #pragma unroll
            for (int q = 0; q < 4; q++) {
                float4 o;
                o.x = (v[4*q+0] - mu) * rs * gs[4*q+0] + bs[4*q+0];
                o.y = (v[4*q+1] - mu) * rs * gs[4*q+1] + bs[4*q+1];
                o.z = (v[4*q+2] - mu) * rs * gs[4*q+2] + bs[4*q+2];
                o.w = (v[4*q+3] - mu) * rs * gs[4*q+3] + bs[4*q+3];
                if (FINAL) {
                    float4 rr = rpg[q];
                    o.x += rr.x; o.y += rr.y; o.z += rr.z; o.w += rr.w;
                }
                o.x = fmaxf(o.x, 0.f); o.y = fmaxf(o.y, 0.f);
                o.z = fmaxf(o.z, 0.f); o.w = fmaxf(o.w, 0.f);
                op[q] = o;
            }
        }
        // next tile's first pack is guarded by the bar_pair at tap-loop top
    }
}

extern "C" void kernel_launch(void* const* d_in, const int* in_sizes, int n_in,
                              void* d_out, int out_size)
{
    const float* x   = (const float*)d_in[0];
    const int*   nbr = (const int*)  d_in[1];
    const float* W1  = (const float*)d_in[2];
    const float* g1  = (const float*)d_in[3];
    const float* b1  = (const float*)d_in[4];
    const float* W2  = (const float*)d_in[5];
    const float* g2  = (const float*)d_in[6];
    const float* b2  = (const float*)d_in[7];
    float* out = (float*)d_out;

    void* hptr = nullptr;
    cudaGetSymbolAddress(&hptr, g_h);
    float* h = (float*)hptr;

    cudaFuncSetAttribute(conv_hmma<false>,
                         cudaFuncAttributeMaxDynamicSharedMemorySize, SMEM_TOTAL);
    cudaFuncSetAttribute(conv_hmma<true>,
                         cudaFuncAttributeMaxDynamicSharedMemorySize, SMEM_TOTAL);

    conv_hmma<false><<<148, THREADS, SMEM_TOTAL>>>(x, nullptr, nbr, W1, g1, b1, h);
    conv_hmma<true ><<<148, THREADS, SMEM_TOTAL>>>(h, x,       nbr, W2, g2, b2, out);
}

// round 13
// speedup vs baseline: 1.2369x; 1.2369x over previous
#include <cuda_runtime.h>
#include <cuda_bf16.h>
#include <cstdint>

#define N_VOX   400000
#define MTILE   384
#define THREADS 768
#define NWARPS  24
#define NTILES  1042          // ceil(400000/384)
#define KK      27

// SMEM: [0) gamma 128B | [128) beta 128B | [1024) W 27*4096B | [111616) A slabs 24*2048B
#define SM_G    0
#define SM_BETA 128
#define SM_W    1024
#define SM_A    111616
#define SMEM_TOTAL (SM_A + NWARPS * 2048)   // 160768

__device__ float g_h[(size_t)N_VOX * 32];

static __device__ __forceinline__ uint32_t smem_u32(const void* p) {
    uint32_t a;
    asm("{ .reg .u64 t; cvta.to.shared.u64 t, %1; cvt.u32.u64 %0, t; }" : "=r"(a) : "l"(p));
    return a;
}
static __device__ __forceinline__ uint32_t pk2(float a, float b) {
    __nv_bfloat162 h = __floats2bfloat162_rn(a, b);
    return *reinterpret_cast<uint32_t*>(&h);
}
static __device__ __forceinline__ float bfh(float x) {
    return __bfloat162float(__float2bfloat16_rn(x));
}
static __device__ __forceinline__ void ldsm4(uint32_t* r, uint32_t addr) {
    asm volatile("ldmatrix.sync.aligned.m8n8.x4.shared.b16 {%0,%1,%2,%3}, [%4];"
                 : "=r"(r[0]), "=r"(r[1]), "=r"(r[2]), "=r"(r[3]) : "r"(addr));
}
static __device__ __forceinline__ void mma16816(float* d, const uint32_t* a,
                                                uint32_t b0, uint32_t b1) {
    asm volatile("mma.sync.aligned.m16n8k16.row.col.f32.bf16.bf16.f32 "
                 "{%0,%1,%2,%3},{%4,%5,%6,%7},{%8,%9},{%0,%1,%2,%3};"
                 : "+f"(d[0]), "+f"(d[1]), "+f"(d[2]), "+f"(d[3])
                 : "r"(a[0]), "r"(a[1]), "r"(a[2]), "r"(a[3]), "r"(b0), "r"(b1));
}

template <bool FINAL>
__global__ void __launch_bounds__(THREADS, 1)
conv_hmma(const float* __restrict__ feats, const float* __restrict__ resid,
          const int* __restrict__ nbr, const float* __restrict__ Wg,
          const float* __restrict__ gamma, const float* __restrict__ beta,
          float* __restrict__ out)
{
    extern __shared__ char smem[];
    const uint32_t sb  = smem_u32(smem);
    const int tid  = threadIdx.x, wid = tid >> 5, lane = tid & 31;
    const int lr   = lane >> 1;          // slab-local row I own (0..15)
    const int hh   = lane & 1;           // which 64B half of the row

    if (tid < 32) {
        ((float*)(smem + SM_G))[tid]    = gamma[tid];
        ((float*)(smem + SM_BETA))[tid] = beta[tid];
    }

    // ---- W prep: [k][cin][cout] -> rows of cout: [Wh 64B | Wl 64B], chunk-swizzled ----
    {
        float* stage = (float*)(smem + SM_A);
        for (int k = 0; k < KK; k++) {
            stage[tid] = Wg[k * 1024 + tid];
            if (tid < 256) stage[768 + tid] = Wg[k * 1024 + 768 + tid];
            __syncthreads();
            if (tid < 256) {
                const int cout = tid & 31, g4 = tid >> 5;   // g4: group of 4 cins
                float w[4], wh[4];
                #pragma unroll
                for (int j = 0; j < 4; j++) {
                    w[j]  = stage[(g4 * 4 + j) * 32 + cout];
                    wh[j] = bfh(w[j]);
                }
                uint2 hi = make_uint2(pk2(w[0], w[1]), pk2(w[2], w[3]));
                uint2 lo = make_uint2(pk2(w[0]-wh[0], w[1]-wh[1]), pk2(w[2]-wh[2], w[3]-wh[3]));
                char* wk = smem + SM_W + k * 4096 + cout * 128;
                const int s = cout & 7, ch = g4 >> 1, half8 = (g4 & 1) * 8;
                *(uint2*)(wk + ((ch ^ s) << 4) + half8)       = hi;
                *(uint2*)(wk + (((4 + ch) ^ s) << 4) + half8) = lo;
            }
            __syncthreads();
        }
    }

    char* slab = smem + SM_A + wid * 2048;          // warp-private 16x128B A tile
    const uint32_t slab_u = sb + SM_A + wid * 2048;
    // LDSM lane constants
    const int b_nrow = (lane & 7) + ((lane >> 4) << 3);   // B: n-row within 16-group
    const int b_chof = (lane >> 3) & 1;                   // B: k-octet select
    const int a_rofs = (lane & 7) + (lane & 8);           // A: row 0..15
    const int a_chof = (lane >> 4);                       // A: k-octet select

    for (int tile = blockIdx.x; tile < NTILES; tile += gridDim.x) {
        const int base = tile * MTILE;
        const int gidx = base + wid * 16 + lr;      // my voxel
        const bool inb = gidx < N_VOX;

        float acc[4][4];
        #pragma unroll
        for (int nb = 0; nb < 4; nb++)
            #pragma unroll
            for (int q = 0; q < 4; q++) acc[nb][q] = 0.f;

        int i0 = inb ? nbr[gidx] : -1;
        int i1 = inb ? nbr[N_VOX + gidx] : -1;
        float4 f[4];
        {
            const bool a0 = (i0 >= 0);
            const float4* p = (const float4*)(feats + (size_t)(a0 ? i0 : 0) * 32 + hh * 16);
            #pragma unroll
            for (int j = 0; j < 4; j++) f[j] = a0 ? p[j] : make_float4(0.f,0.f,0.f,0.f);
        }

        #pragma unroll 1
        for (int k = 0; k < KK; k++) {
            const int i2 = (k + 2 < KK && inb) ? nbr[(size_t)(k + 2) * N_VOX + gidx] : -1;
            const bool act = (i0 >= 0);
            const uint32_t mask = __ballot_sync(0xffffffffu, act);

            __syncwarp();   // prior tap's LDSM / prior tile's epilogue reads done
            if (mask) {     // warp's 16-row group consumed -> store my half (zeros ok)
                uint32_t hi[8], lo[8];
                if (act) {
                    #pragma unroll
                    for (int j = 0; j < 4; j++) {
                        float4 q = f[j];
                        float hx = bfh(q.x), hy = bfh(q.y), hz = bfh(q.z), hw = bfh(q.w);
                        hi[2*j]   = pk2(q.x, q.y);       hi[2*j+1] = pk2(q.z, q.w);
                        lo[2*j]   = pk2(q.x-hx, q.y-hy); lo[2*j+1] = pk2(q.z-hz, q.w-hw);
                    }
                } else {
                    #pragma unroll
                    for (int j = 0; j < 8; j++) { hi[j] = 0u; lo[j] = 0u; }
                }
                char* arow = slab + lr * 128;
                const int s = lr & 7;
                const int c0 = hh * 2;
                *(uint4*)(arow + (((c0    ) ^ s) << 4)) = make_uint4(hi[0], hi[1], hi[2], hi[3]);
                *(uint4*)(arow + (((c0 + 1) ^ s) << 4)) = make_uint4(hi[4], hi[5], hi[6], hi[7]);
                *(uint4*)(arow + (((4 + c0    ) ^ s) << 4)) = make_uint4(lo[0], lo[1], lo[2], lo[3]);
                *(uint4*)(arow + (((4 + c0 + 1) ^ s) << 4)) = make_uint4(lo[4], lo[5], lo[6], lo[7]);
            }

            // prefetch next tap's features (f consumed by pack above)
            {
                const bool an = (i1 >= 0);
                const float4* p = (const float4*)(feats + (size_t)(an ? i1 : 0) * 32 + hh * 16);
                #pragma unroll
                for (int j = 0; j < 4; j++) f[j] = an ? p[j] : make_float4(0.f,0.f,0.f,0.f);
            }

            if (mask) {
                __syncwarp();   // A slab visible to whole warp
                const uint32_t wbase = sb + SM_W + k * 4096;
                #pragma unroll
                for (int kb = 0; kb < 2; kb++) {
                    uint32_t ah[4], al[4], bh[2][4], bl[2][4];
                    {
                        const int s = a_rofs & 7;
                        const uint32_t ra = slab_u + a_rofs * 128;
                        ldsm4(ah, ra + (((2*kb + a_chof) ^ s) << 4));
                        ldsm4(al, ra + (((4 + 2*kb + a_chof) ^ s) << 4));
                    }
                    #pragma unroll
                    for (int np = 0; np < 2; np++) {
                        const int n0 = np * 16 + b_nrow;
                        const int s  = n0 & 7;
                        const uint32_t rb = wbase + n0 * 128;
                        ldsm4(bh[np], rb + (((2*kb + b_chof) ^ s) << 4));
                        ldsm4(bl[np], rb + (((4 + 2*kb + b_chof) ^ s) << 4));
                    }
                    #pragma unroll
                    for (int nb = 0; nb < 4; nb++) {
                        const int np = nb >> 1, sel = (nb & 1) * 2;
                        mma16816(acc[nb], ah, bh[np][sel], bh[np][sel+1]);
                        mma16816(acc[nb], al, bh[np][sel], bh[np][sel+1]);
                        mma16816(acc[nb], ah, bl[np][sel], bl[np][sel+1]);
                    }
                }
            }
            i0 = i1; i1 = i2;
        }

        // ---- epilogue: acc frags -> f32 rows in my slab -> per-half-row LN ----
        __syncwarp();           // warp's last LDSM of A done before overwrite
        {
            const int r0 = lane >> 2;               // 0..7 ; rows r0 and r0+8
            const int cb = (lane & 3) * 8;
            const int s  = r0 & 7;                  // == (r0+8)&7
            char* rp  = slab + r0 * 128;
            char* rp8 = slab + (r0 + 8) * 128;
            #pragma unroll
            for (int nb = 0; nb < 4; nb++) {
                const int byte0 = nb * 32 + cb;
                const int ch = byte0 >> 4, off = byte0 & 15;
                *(float2*)(rp  + ((ch ^ s) << 4) + off) = make_float2(acc[nb][0], acc[nb][1]);
                *(float2*)(rp8 + ((ch ^ s) << 4) + off) = make_float2(acc[nb][2], acc[nb][3]);
            }
        }
        __syncwarp();
        if (inb) {
            float v[16];
            const int s = lr & 7;
            const char* rp = slab + lr * 128;
            #pragma unroll
            for (int j = 0; j < 4; j++) {
                const int c = hh * 4 + j;
                float4 t4 = *(const float4*)(rp + ((c ^ s) << 4));
                v[4*j] = t4.x; v[4*j+1] = t4.y; v[4*j+2] = t4.z; v[4*j+3] = t4.w;
            }
            float sum = 0.f;
            #pragma unroll
            for (int c = 0; c < 16; c++) sum += v[c];
            sum += __shfl_xor_sync(0xffffffffu, sum, 1);   // partner = other half of row
            const float mu = sum * (1.0f / 32.0f);
            float var = 0.f;
            #pragma unroll
            for (int c = 0; c < 16; c++) { float d = v[c] - mu; var += d * d; }
            var += __shfl_xor_sync(0xffffffffu, var, 1);
            const float rs = rsqrtf(var * (1.0f / 32.0f) + 1e-6f);
            const float* gs = (const float*)(smem + SM_G)    + hh * 16;
            const float* bs = (const float*)(smem + SM_BETA) + hh * 16;
            float4* op = (float4*)(out + (size_t)gidx * 32 + hh * 16);
            const float4* rpg = FINAL ? (const float4*)(resid + (size_t)gidx * 32 + hh * 16) : nullptr;
            #pragma unroll
            for (int q = 0; q < 4; q++) {
                float4 o;
                o.x = (v[4*q+0] - mu) * rs * gs[4*q+0] + bs[4*q+0];
                o.y = (v[4*q+1] - mu) * rs * gs[4*q+1] + bs[4*q+1];
                o.z = (v[4*q+2] - mu) * rs * gs[4*q+2] + bs[4*q+2];
                o.w = (v[4*q+3] - mu) * rs * gs[4*q+3] + bs[4*q+3];
                if (FINAL) {
                    float4 rr = rpg[q];
                    o.x += rr.x; o.y += rr.y; o.z += rr.z; o.w += rr.w;
                }
                o.x = fmaxf(o.x, 0.f); o.y = fmaxf(o.y, 0.f);
                o.z = fmaxf(o.z, 0.f); o.w = fmaxf(o.w, 0.f);
                op[q] = o;
            }
        }
        // next tile's first pack is guarded by the __syncwarp at tap-loop top
    }
}

extern "C" void kernel_launch(void* const* d_in, const int* in_sizes, int n_in,
                              void* d_out, int out_size)
{
    const float* x   = (const float*)d_in[0];
    const int*   nbr = (const int*)  d_in[1];
    const float* W1  = (const float*)d_in[2];
    const float* g1  = (const float*)d_in[3];
    const float* b1  = (const float*)d_in[4];
    const float* W2  = (const float*)d_in[5];
    const float* g2  = (const float*)d_in[6];
    const float* b2  = (const float*)d_in[7];
    float* out = (float*)d_out;

    void* hptr = nullptr;
    cudaGetSymbolAddress(&hptr, g_h);
    float* h = (float*)hptr;

    cudaFuncSetAttribute(conv_hmma<false>,
                         cudaFuncAttributeMaxDynamicSharedMemorySize, SMEM_TOTAL);
    cudaFuncSetAttribute(conv_hmma<true>,
                         cudaFuncAttributeMaxDynamicSharedMemorySize, SMEM_TOTAL);

    conv_hmma<false><<<148, THREADS, SMEM_TOTAL>>>(x, nullptr, nbr, W1, g1, b1, h);
    conv_hmma<true ><<<148, THREADS, SMEM_TOTAL>>>(h, x,       nbr, W2, g2, b2, out);
}

// round 16
// speedup vs baseline: 1.6674x; 1.3480x over previous
#include <cuda_runtime.h>
#include <cuda_fp16.h>
#include <cstdint>

#define N_VOX   400000
#define MTILE   384
#define THREADS 768
#define NWARPS  24
#define NTILES  1042          // ceil(400000/384)
#define KK      27

// SMEM: gamma 128B | beta 128B | W 27*2560B (fp16, stride-80 rows) |
//       A slabs 24*1280B (fp16, stride-80) | epilogue slabs 24*2048B (f32, XOR-swizzled)
#define SM_G    0
#define SM_BETA 128
#define SM_W    1024
#define W_TAP   2560          // 32 cout rows * 80B
#define SM_AS   (SM_W + KK * W_TAP)          // 70144
#define SM_EPI  (SM_AS + NWARPS * 1280)      // 100864
#define SMEM_TOTAL (SM_EPI + NWARPS * 2048)  // 150016

__device__ float g_h[(size_t)N_VOX * 32];

static __device__ __forceinline__ uint32_t smem_u32(const void* p) {
    uint32_t a;
    asm("{ .reg .u64 t; cvta.to.shared.u64 t, %1; cvt.u32.u64 %0, t; }" : "=r"(a) : "l"(p));
    return a;
}
static __device__ __forceinline__ uint32_t pkh(float a, float b) {
    __half2 h = __floats2half2_rn(a, b);
    return *reinterpret_cast<uint32_t*>(&h);
}
static __device__ __forceinline__ void ldsm4(uint32_t* r, uint32_t addr) {
    asm volatile("ldmatrix.sync.aligned.m8n8.x4.shared.b16 {%0,%1,%2,%3}, [%4];"
                 : "=r"(r[0]), "=r"(r[1]), "=r"(r[2]), "=r"(r[3]) : "r"(addr));
}
static __device__ __forceinline__ void mma16816(float* d, const uint32_t* a,
                                                uint32_t b0, uint32_t b1) {
    asm volatile("mma.sync.aligned.m16n8k16.row.col.f32.f16.f16.f32 "
                 "{%0,%1,%2,%3},{%4,%5,%6,%7},{%8,%9},{%0,%1,%2,%3};"
                 : "+f"(d[0]), "+f"(d[1]), "+f"(d[2]), "+f"(d[3])
                 : "r"(a[0]), "r"(a[1]), "r"(a[2]), "r"(a[3]), "r"(b0), "r"(b1));
}

template <bool FINAL>
__global__ void __launch_bounds__(THREADS, 1)
conv_hmma(const float* __restrict__ feats, const float* __restrict__ resid,
          const int* __restrict__ nbr, const float* __restrict__ Wg,
          const float* __restrict__ gamma, const float* __restrict__ beta,
          float* __restrict__ out)
{
    extern __shared__ char smem[];
    const uint32_t sb  = smem_u32(smem);
    const int tid  = threadIdx.x, wid = tid >> 5, lane = tid & 31;
    const int lr   = lane & 15;          // slab-local row I own (0..15)
    const int hh   = lane >> 4;          // which 32B(fp16)/64B(f32) half of the row

    if (tid < 32) {
        ((float*)(smem + SM_G))[tid]    = gamma[tid];
        ((float*)(smem + SM_BETA))[tid] = beta[tid];
    }

    // ---- W prep: [k][cin][cout] -> fp16 rows of cout (32 cin, 64B) at stride 80 ----
    {
        float* stage = (float*)(smem + SM_EPI);
        for (int k = 0; k < KK; k++) {
            stage[tid] = Wg[k * 1024 + tid];
            if (tid < 256) stage[768 + tid] = Wg[k * 1024 + 768 + tid];
            __syncthreads();
            if (tid < 256) {
                const int cout = tid & 31, g4 = tid >> 5;   // g4: group of 4 cins
                float w0 = stage[(g4 * 4 + 0) * 32 + cout];
                float w1 = stage[(g4 * 4 + 1) * 32 + cout];
                float w2 = stage[(g4 * 4 + 2) * 32 + cout];
                float w3 = stage[(g4 * 4 + 3) * 32 + cout];
                *(uint2*)(smem + SM_W + k * W_TAP + cout * 80 + g4 * 8) =
                    make_uint2(pkh(w0, w1), pkh(w2, w3));
            }
            __syncthreads();
        }
    }

    char* slab = smem + SM_AS + wid * 1280;          // warp-private 16x80B fp16 A tile
    const uint32_t slab_u = sb + SM_AS + wid * 1280;
    char* epi  = smem + SM_EPI + wid * 2048;         // warp-private 16x128B f32 tile
    // LDSM lane constants (stride-80, no XOR)
    const int b_nrow = (lane & 7) + ((lane >> 4) << 3);   // B: n-row within 16-group
    const int b_chof = (lane >> 3) & 1;                   // B: k-octet select
    const uint32_t a_addr0 = slab_u + (lane & 15) * 80 + (lane >> 4) * 16;  // + kb*32
    const uint32_t b_off0  = (uint32_t)(b_nrow * 80 + b_chof * 16);         // + np*1280 + kb*32

    for (int tile = blockIdx.x; tile < NTILES; tile += gridDim.x) {
        const int base = tile * MTILE;
        const int gidx = base + wid * 16 + lr;      // my voxel
        const bool inb = gidx < N_VOX;

        float acc[4][4];
        #pragma unroll
        for (int nb = 0; nb < 4; nb++)
            #pragma unroll
            for (int q = 0; q < 4; q++) acc[nb][q] = 0.f;

        int i0 = inb ? nbr[gidx] : -1;
        int i1 = inb ? nbr[N_VOX + gidx] : -1;
        float4 f[4];
        {
            const bool a0 = (i0 >= 0);
            const float4* p = (const float4*)(feats + (size_t)(a0 ? i0 : 0) * 32 + hh * 16);
            #pragma unroll
            for (int j = 0; j < 4; j++) f[j] = a0 ? p[j] : make_float4(0.f,0.f,0.f,0.f);
        }

        #pragma unroll 1
        for (int k = 0; k < KK; k++) {
            const int i2 = (k + 2 < KK && inb) ? nbr[(size_t)(k + 2) * N_VOX + gidx] : -1;
            const bool act = (i0 >= 0);
            const uint32_t mask = __ballot_sync(0xffffffffu, act);

            __syncwarp();   // prior tap's LDSM / prior tile's epilogue done with slab
            if (mask) {     // warp's 16-row group consumed -> store my half (zeros ok)
                uint32_t p0 = 0u, p1 = 0u, p2 = 0u, p3 = 0u,
                         p4 = 0u, p5 = 0u, p6 = 0u, p7 = 0u;
                if (act) {
                    p0 = pkh(f[0].x, f[0].y); p1 = pkh(f[0].z, f[0].w);
                    p2 = pkh(f[1].x, f[1].y); p3 = pkh(f[1].z, f[1].w);
                    p4 = pkh(f[2].x, f[2].y); p5 = pkh(f[2].z, f[2].w);
                    p6 = pkh(f[3].x, f[3].y); p7 = pkh(f[3].z, f[3].w);
                }
                char* arow = slab + lr * 80 + hh * 32;
                *(uint4*)(arow)      = make_uint4(p0, p1, p2, p3);
                *(uint4*)(arow + 16) = make_uint4(p4, p5, p6, p7);
            }

            // prefetch next tap's features (f consumed by pack above)
            {
                const bool an = (i1 >= 0);
                const float4* p = (const float4*)(feats + (size_t)(an ? i1 : 0) * 32 + hh * 16);
                #pragma unroll
                for (int j = 0; j < 4; j++) f[j] = an ? p[j] : make_float4(0.f,0.f,0.f,0.f);
            }

            if (mask) {
                __syncwarp();   // A slab visible to whole warp
                const uint32_t wbase = sb + SM_W + k * W_TAP + b_off0;
                #pragma unroll
                for (int kb = 0; kb < 2; kb++) {
                    uint32_t a[4], b[2][4];
                    ldsm4(a, a_addr0 + kb * 32);
                    ldsm4(b[0], wbase + kb * 32);
                    ldsm4(b[1], wbase + 1280 + kb * 32);
                    #pragma unroll
                    for (int nb = 0; nb < 4; nb++) {
                        const int np = nb >> 1, sel = (nb & 1) * 2;
                        mma16816(acc[nb], a, b[np][sel], b[np][sel + 1]);
                    }
                }
            }
            i0 = i1; i1 = i2;
        }

        // ---- epilogue: acc frags -> f32 rows in epi slab -> per-half-row LN ----
        __syncwarp();
        {
            const int r0 = lane >> 2;               // 0..7 ; rows r0 and r0+8
            const int cb = (lane & 3) * 8;
            const int s  = r0 & 7;                  // == (r0+8)&7
            char* rp  = epi + r0 * 128;
            char* rp8 = epi + (r0 + 8) * 128;
            #pragma unroll
            for (int nb = 0; nb < 4; nb++) {
                const int byte0 = nb * 32 + cb;
                const int ch = byte0 >> 4, off = byte0 & 15;
                *(float2*)(rp  + ((ch ^ s) << 4) + off) = make_float2(acc[nb][0], acc[nb][1]);
                *(float2*)(rp8 + ((ch ^ s) << 4) + off) = make_float2(acc[nb][2], acc[nb][3]);
            }
        }
        __syncwarp();
        if (inb) {
            float v[16];
            const int s = lr & 7;
            const char* rp = epi + lr * 128;
            #pragma unroll
            for (int j = 0; j < 4; j++) {
                const int c = hh * 4 + j;
                float4 t4 = *(const float4*)(rp + ((c ^ s) << 4));
                v[4*j] = t4.x; v[4*j+1] = t4.y; v[4*j+2] = t4.z; v[4*j+3] = t4.w;
            }
            float sum = 0.f;
            #pragma unroll
            for (int c = 0; c < 16; c++) sum += v[c];
            sum += __shfl_xor_sync(0xffffffffu, sum, 16);  // partner = other half of row
            const float mu = sum * (1.0f / 32.0f);
            float var = 0.f;
            #pragma unroll
            for (int c = 0; c < 16; c++) { float d = v[c] - mu; var += d * d; }
            var += __shfl_xor_sync(0xffffffffu, var, 16);
            const float rs = rsqrtf(var * (1.0f / 32.0f) + 1e-6f);
            const float* gs = (const float*)(smem + SM_G)    + hh * 16;
            const float* bs = (const float*)(smem + SM_BETA) + hh * 16;
            float4* op = (float4*)(out + (size_t)gidx * 32 + hh * 16);
            const float4* rpg = FINAL ? (const float4*)(resid + (size_t)gidx * 32 + hh * 16) : nullptr;
            #pragma unroll
            for (int q = 0; q < 4; q++) {
                float4 o;
                o.x = (v[4*q+0] - mu) * rs * gs[4*q+0] + bs[4*q+0];
                o.y = (v[4*q+1] - mu) * rs * gs[4*q+1] + bs[4*q+1];
                o.z = (v[4*q+2] - mu) * rs * gs[4*q+2] + bs[4*q+2];
                o.w = (v[4*q+3] - mu) * rs * gs[4*q+3] + bs[4*q+3];
                if (FINAL) {
                    float4 rr = rpg[q];
                    o.x += rr.x; o.y += rr.y; o.z += rr.z; o.w += rr.w;
                }
                o.x = fmaxf(o.x, 0.f); o.y = fmaxf(o.y, 0.f);
                o.z = fmaxf(o.z, 0.f); o.w = fmaxf(o.w, 0.f);
                op[q] = o;
            }
        }
        // next tile's first pack is guarded by the __syncwarp at tap-loop top
    }
}

extern "C" void kernel_launch(void* const* d_in, const int* in_sizes, int n_in,
                              void* d_out, int out_size)
{
    const float* x   = (const float*)d_in[0];
    const int*   nbr = (const int*)  d_in[1];
    const float* W1  = (const float*)d_in[2];
    const float* g1  = (const float*)d_in[3];
    const float* b1  = (const float*)d_in[4];
    const float* W2  = (const float*)d_in[5];
    const float* g2  = (const float*)d_in[6];
    const float* b2  = (const float*)d_in[7];
    float* out = (float*)d_out;

    void* hptr = nullptr;
    cudaGetSymbolAddress(&hptr, g_h);
    float* h = (float*)hptr;

    cudaFuncSetAttribute(conv_hmma<false>,
                         cudaFuncAttributeMaxDynamicSharedMemorySize, SMEM_TOTAL);
    cudaFuncSetAttribute(conv_hmma<true>,
                         cudaFuncAttributeMaxDynamicSharedMemorySize, SMEM_TOTAL);

    conv_hmma<false><<<148, THREADS, SMEM_TOTAL>>>(x, nullptr, nbr, W1, g1, b1, h);
    conv_hmma<true ><<<148, THREADS, SMEM_TOTAL>>>(h, x,       nbr, W2, g2, b2, out);
}

// round 17
// speedup vs baseline: 1.8568x; 1.1136x over previous
#include <cuda_runtime.h>
#include <cuda_fp16.h>
#include <cstdint>

#define N_VOX   400000
#define MTILE   512
#define THREADS 1024
#define NWARPS  32
#define NTILES  782           // ceil(400000/512)
#define KK      27

// SMEM: gamma 128B | beta 128B | W 27*2560B (fp16, stride-80 rows) |
//       A slabs 32 warps * 2 bufs * 1280B (fp16, stride-80)
#define SM_G    0
#define SM_BETA 128
#define SM_W    1024
#define W_TAP   2560          // 32 cout rows * 80B
#define SM_AS   (SM_W + KK * W_TAP)              // 70144
#define SMEM_TOTAL (SM_AS + NWARPS * 2 * 1280)   // 152064

__device__ float g_h[(size_t)N_VOX * 32];

static __device__ __forceinline__ uint32_t smem_u32(const void* p) {
    uint32_t a;
    asm("{ .reg .u64 t; cvta.to.shared.u64 t, %1; cvt.u32.u64 %0, t; }" : "=r"(a) : "l"(p));
    return a;
}
static __device__ __forceinline__ uint32_t pkh(float a, float b) {
    __half2 h = __floats2half2_rn(a, b);
    return *reinterpret_cast<uint32_t*>(&h);
}
static __device__ __forceinline__ void ldsm4(uint32_t* r, uint32_t addr) {
    asm volatile("ldmatrix.sync.aligned.m8n8.x4.shared.b16 {%0,%1,%2,%3}, [%4];"
                 : "=r"(r[0]), "=r"(r[1]), "=r"(r[2]), "=r"(r[3]) : "r"(addr));
}
static __device__ __forceinline__ void mma16816(float* d, const uint32_t* a,
                                                uint32_t b0, uint32_t b1) {
    asm volatile("mma.sync.aligned.m16n8k16.row.col.f32.f16.f16.f32 "
                 "{%0,%1,%2,%3},{%4,%5,%6,%7},{%8,%9},{%0,%1,%2,%3};"
                 : "+f"(d[0]), "+f"(d[1]), "+f"(d[2]), "+f"(d[3])
                 : "r"(a[0]), "r"(a[1]), "r"(a[2]), "r"(a[3]), "r"(b0), "r"(b1));
}

template <bool FINAL>
__global__ void __launch_bounds__(THREADS, 1)
conv_hmma(const float* __restrict__ feats, const float* __restrict__ resid,
          const int* __restrict__ nbr, const float* __restrict__ Wg,
          const float* __restrict__ gamma, const float* __restrict__ beta,
          float* __restrict__ out)
{
    extern __shared__ char smem[];
    const uint32_t sb  = smem_u32(smem);
    const int tid  = threadIdx.x, wid = tid >> 5, lane = tid & 31;
    const int lr   = lane & 15;          // slab-local row I gather/pack (0..15)
    const int hh   = lane >> 4;          // 32B half of the fp16 row I pack

    if (tid < 32) {
        ((float*)(smem + SM_G))[tid]    = gamma[tid];
        ((float*)(smem + SM_BETA))[tid] = beta[tid];
    }

    // ---- W prep: [k][cin][cout] -> fp16 rows of cout (32 cin = 64B) at stride 80 ----
    {
        float* stage = (float*)(smem + SM_AS);
        for (int k = 0; k < KK; k++) {
            stage[tid] = Wg[k * 1024 + tid];
            __syncthreads();
            if (tid < 256) {
                const int cout = tid & 31, g4 = tid >> 5;   // g4: group of 4 cins
                float w0 = stage[(g4 * 4 + 0) * 32 + cout];
                float w1 = stage[(g4 * 4 + 1) * 32 + cout];
                float w2 = stage[(g4 * 4 + 2) * 32 + cout];
                float w3 = stage[(g4 * 4 + 3) * 32 + cout];
                *(uint2*)(smem + SM_W + k * W_TAP + cout * 80 + g4 * 8) =
                    make_uint2(pkh(w0, w1), pkh(w2, w3));
            }
            __syncthreads();
        }
    }

    char* slab = smem + SM_AS + wid * 2560;       // 2 x 1280B warp-private A bufs
    const uint32_t slab_u = sb + SM_AS + wid * 2560;
    // LDSM lane constants (stride-80, no XOR swizzle)
    const int b_nrow = (lane & 7) + ((lane >> 4) << 3);
    const int b_chof = (lane >> 3) & 1;
    const uint32_t a_off0 = (uint32_t)(lr * 80 + hh * 16);              // + buf*1280 + kb*32
    const uint32_t b_off0 = (uint32_t)(b_nrow * 80 + b_chof * 16);      // + np*1280 + kb*32

    for (int tile = blockIdx.x; tile < NTILES; tile += gridDim.x) {
        const int base = tile * MTILE;
        const int gidx = base + wid * 16 + lr;    // my voxel
        const bool inb = gidx < N_VOX;

        float acc[4][4];
        #pragma unroll
        for (int nb = 0; nb < 4; nb++)
            #pragma unroll
            for (int q = 0; q < 4; q++) acc[nb][q] = 0.f;

        // prologue: gather tap 0
        int i_nxt = inb ? nbr[N_VOX + gidx] : -1;
        bool act;
        float4 f[4];
        {
            int i0 = inb ? nbr[gidx] : -1;
            act = (i0 >= 0);
            const float4* p = (const float4*)(feats + (size_t)(act ? i0 : 0) * 32 + hh * 16);
            #pragma unroll
            for (int j = 0; j < 4; j++) f[j] = act ? p[j] : make_float4(0.f,0.f,0.f,0.f);
        }

        #pragma unroll 1
        for (int k = 0; k < KK; k++) {
            const uint32_t mask = __ballot_sync(0xffffffffu, act);
            const uint32_t bsel = (uint32_t)(k & 1) * 1280u;

            if (mask) {   // pack tap k into buf k&1 (zeros for inactive lanes)
                uint32_t p0=0u,p1=0u,p2=0u,p3=0u,p4=0u,p5=0u,p6=0u,p7=0u;
                if (act) {
                    p0 = pkh(f[0].x, f[0].y); p1 = pkh(f[0].z, f[0].w);
                    p2 = pkh(f[1].x, f[1].y); p3 = pkh(f[1].z, f[1].w);
                    p4 = pkh(f[2].x, f[2].y); p5 = pkh(f[2].z, f[2].w);
                    p6 = pkh(f[3].x, f[3].y); p7 = pkh(f[3].z, f[3].w);
                }
                char* arow = slab + bsel + lr * 80 + hh * 32;
                *(uint4*)(arow)      = make_uint4(p0, p1, p2, p3);
                *(uint4*)(arow + 16) = make_uint4(p4, p5, p6, p7);
            }

            // prefetch tap k+1 gathers (consumed by pack next iteration)
            const bool act_n = (i_nxt >= 0);
            {
                const float4* p = (const float4*)(feats + (size_t)(act_n ? i_nxt : 0) * 32 + hh * 16);
                #pragma unroll
                for (int j = 0; j < 4; j++) f[j] = act_n ? p[j] : make_float4(0.f,0.f,0.f,0.f);
            }
            i_nxt = (k + 2 < KK && inb) ? nbr[(size_t)(k + 2) * N_VOX + gidx] : -1;

            __syncwarp();   // pack visible to whole warp before LDSM
            if (mask) {
                const uint32_t abase = slab_u + bsel + a_off0;
                const uint32_t wbase = sb + SM_W + k * W_TAP + b_off0;
                #pragma unroll
                for (int kb = 0; kb < 2; kb++) {
                    uint32_t a[4], b[2][4];
                    ldsm4(a, abase + kb * 32);
                    ldsm4(b[0], wbase + kb * 32);
                    ldsm4(b[1], wbase + 1280 + kb * 32);
                    #pragma unroll
                    for (int nb = 0; nb < 4; nb++) {
                        const int np = nb >> 1, sel = (nb & 1) * 2;
                        mma16816(acc[nb], a, b[np][sel], b[np][sel + 1]);
                    }
                }
            }
            act = act_n;
        }

        // ---- epilogue directly on fragments ----
        // thread owns rows ra=lane>>2, rb=ra+8 (slab-local), cols nb*8+(lane&3)*2+{0,1}
        {
            float sa = 0.f, sbv = 0.f;
            #pragma unroll
            for (int nb = 0; nb < 4; nb++) {
                sa  += acc[nb][0] + acc[nb][1];
                sbv += acc[nb][2] + acc[nb][3];
            }
            sa  += __shfl_xor_sync(0xffffffffu, sa, 1);
            sa  += __shfl_xor_sync(0xffffffffu, sa, 2);
            sbv += __shfl_xor_sync(0xffffffffu, sbv, 1);
            sbv += __shfl_xor_sync(0xffffffffu, sbv, 2);
            const float mua = sa  * (1.0f / 32.0f);
            const float mub = sbv * (1.0f / 32.0f);
            float va = 0.f, vb = 0.f;
            #pragma unroll
            for (int nb = 0; nb < 4; nb++) {
                float d0 = acc[nb][0] - mua, d1 = acc[nb][1] - mua;
                float d2 = acc[nb][2] - mub, d3 = acc[nb][3] - mub;
                va += d0 * d0 + d1 * d1;
                vb += d2 * d2 + d3 * d3;
            }
            va += __shfl_xor_sync(0xffffffffu, va, 1);
            va += __shfl_xor_sync(0xffffffffu, va, 2);
            vb += __shfl_xor_sync(0xffffffffu, vb, 1);
            vb += __shfl_xor_sync(0xffffffffu, vb, 2);
            const float rsa = rsqrtf(va * (1.0f / 32.0f) + 1e-6f);
            const float rsb = rsqrtf(vb * (1.0f / 32.0f) + 1e-6f);

            const int ra = base + wid * 16 + (lane >> 2);
            const int rb = ra + 8;
            const bool ia = ra < N_VOX, ib = rb < N_VOX;
            const int colb = (lane & 3) * 2;
            const float* gs = (const float*)(smem + SM_G);
            const float* bs = (const float*)(smem + SM_BETA);
            #pragma unroll
            for (int nb = 0; nb < 4; nb++) {
                const int col = nb * 8 + colb;
                const float2 g2 = *(const float2*)(gs + col);
                const float2 b2 = *(const float2*)(bs + col);
                if (ia) {
                    float ox = (acc[nb][0] - mua) * rsa * g2.x + b2.x;
                    float oy = (acc[nb][1] - mua) * rsa * g2.y + b2.y;
                    if (FINAL) {
                        float2 rr = *(const float2*)(resid + (size_t)ra * 32 + col);
                        ox += rr.x; oy += rr.y;
                    }
                    *(float2*)(out + (size_t)ra * 32 + col) =
                        make_float2(fmaxf(ox, 0.f), fmaxf(oy, 0.f));
                }
                if (ib) {
                    float ox = (acc[nb][2] - mub) * rsb * g2.x + b2.x;
                    float oy = (acc[nb][3] - mub) * rsb * g2.y + b2.y;
                    if (FINAL) {
                        float2 rr = *(const float2*)(resid + (size_t)rb * 32 + col);
                        ox += rr.x; oy += rr.y;
                    }
                    *(float2*)(out + (size_t)rb * 32 + col) =
                        make_float2(fmaxf(ox, 0.f), fmaxf(oy, 0.f));
                }
            }
        }
        // next tile's pack into buf0 is safe: its last reader was 2 taps back
    }
}

extern "C" void kernel_launch(void* const* d_in, const int* in_sizes, int n_in,
                              void* d_out, int out_size)
{
    const float* x   = (const float*)d_in[0];
    const int*   nbr = (const int*)  d_in[1];
    const float* W1  = (const float*)d_in[2];
    const float* g1  = (const float*)d_in[3];
    const float* b1  = (const float*)d_in[4];
    const float* W2  = (const float*)d_in[5];
    const float* g2  = (const float*)d_in[6];
    const float* b2  = (const float*)d_in[7];
    float* out = (float*)d_out;

    void* hptr = nullptr;
    cudaGetSymbolAddress(&hptr, g_h);
    float* h = (float*)hptr;

    cudaFuncSetAttribute(conv_hmma<false>,
                         cudaFuncAttributeMaxDynamicSharedMemorySize, SMEM_TOTAL);
    cudaFuncSetAttribute(conv_hmma<true>,
                         cudaFuncAttributeMaxDynamicSharedMemorySize, SMEM_TOTAL);

    conv_hmma<false><<<148, THREADS, SMEM_TOTAL>>>(x, nullptr, nbr, W1, g1, b1, h);
    conv_hmma<true ><<<148, THREADS, SMEM_TOTAL>>>(h, x,       nbr, W2, g2, b2, out);
}